// round 7
// baseline (speedup 1.0000x reference)
#include <cuda_runtime.h>

// Dynamic local filtering: out[n,c,h,w] = sum_{k1,k2} x_pad[n,c,h+k1,w+k2] * kern[n,(c*25+k1*5+k2),h,w]
// then leaky_relu(0.2). Replicate padding. Shapes fixed: N=4, C=8, H=W=256, K=5.
// R5: full-width contiguous tiles (256x2) + 2 px/thread so the 25-deep weight
//     preload costs 50 regs -> 3 CTAs/SM. Contiguity (R4 win) + occupancy to
//     close DRAM coverage gaps during per-CTA compute phases.

#define WID 256
#define HEI 256
#define HW  (WID * HEI)
#define TW  256   // full width: 128 threads x 2 px per row
#define TH  2     // rows per CTA
#define SW  (TW + 4)   // 260 floats per smem row (float2/float4 aligned)
#define SH  (TH + 4)   // 6

__global__ __launch_bounds__(256, 3)
void dynconv5x5_kernel(const float* __restrict__ x,
                       const float* __restrict__ kern,
                       float* __restrict__ out)
{
    __shared__ float tile[SH * SW];

    const int plane = blockIdx.z;           // n*C + c, 0..31
    const int by = blockIdx.y * TH;
    const int tid = threadIdx.x;            // 0..255

    const int lx = tid & 127;               // 128 threads across the row
    const int ly = tid >> 7;                // 2 rows
    const int w0 = lx * 2;                  // first of 2 pixels handled
    const int h  = by + ly;

    // Weight pointer: per tap t, this thread's 2 pixels' weights are one float2.
    const float2* __restrict__ k2 = (const float2*)kern
        + (size_t)plane * 25 * (HW / 2)
        + (size_t)(h * WID + w0) / 2;

    // ---- Issue ALL 25 independent LDG.64 weight loads up front (MLP=25). ----
    float2 kv[25];
    #pragma unroll
    for (int t = 0; t < 25; t++) {
        kv[t] = __ldcs(&k2[(size_t)t * (HW / 2)]);
    }

    // Cooperative load of x tile with halo; replicate padding via clamp.
    // (Overlaps with the in-flight weight loads; halo re-reads are L2 hits.)
    const float* __restrict__ xp = x + (size_t)plane * HW;
    #pragma unroll
    for (int i = tid; i < SH * SW; i += 256) {
        int sy = i / SW;
        int sx = i - sy * SW;
        int gy = by + sy - 2; gy = max(0, min(HEI - 1, gy));
        int gx = sx - 2;      gx = max(0, min(WID - 1, gx));
        tile[i] = xp[gy * WID + gx];
    }
    __syncthreads();

    float ax = 0.f, ay = 0.f;

    #pragma unroll
    for (int dy = 0; dy < 5; dy++) {
        // 6 consecutive x values covering the 2 pixels' horizontal extents
        const float2* srow = (const float2*)&tile[(ly + dy) * SW + w0];
        float2 s0 = srow[0];
        float2 s1 = srow[1];
        float2 s2 = srow[2];
        float s[6] = { s0.x, s0.y, s1.x, s1.y, s2.x, s2.y };

        #pragma unroll
        for (int dx = 0; dx < 5; dx++) {
            float2 w = kv[dy * 5 + dx];
            ax += w.x * s[dx + 0];
            ay += w.y * s[dx + 1];
        }
    }

    // leaky_relu(0.2)
    ax = ax >= 0.f ? ax : 0.2f * ax;
    ay = ay >= 0.f ? ay : 0.2f * ay;

    float2 r = make_float2(ax, ay);
    __stcs(&((float2*)out)[(size_t)plane * (HW / 2) + (size_t)(h * WID + w0) / 2], r);
}

extern "C" void kernel_launch(void* const* d_in, const int* in_sizes, int n_in,
                              void* d_out, int out_size)
{
    const float* x    = (const float*)d_in[0];   // (4, 8, 256, 256)
    const float* kern = (const float*)d_in[1];   // (4, 200, 256, 256)
    float* out = (float*)d_out;                  // (4, 8, 256, 256)

    dim3 block(256, 1, 1);
    dim3 grid(1, HEI / TH, 32);                  // (1, 128, 32) = 4096 CTAs
    dynconv5x5_kernel<<<grid, block>>>(x, kern, out);
}

// round 8
// speedup vs baseline: 1.0692x; 1.0692x over previous
#include <cuda_runtime.h>

// Dynamic local filtering: out[n,c,h,w] = sum_{k1,k2} x_pad[n,c,h+k1,w+k2] * kern[n,(c*25+k1*5+k2),h,w]
// then leaky_relu(0.2). Replicate padding. Shapes fixed: N=4, C=8, H=W=256, K=5.
// R6: R4 layout (full-width 256x4 tiles, 4px/thread LDG.128, contiguous 4KB/tap)
//     + SPLIT weight preload (13 then 12, pinned by a compiler barrier) so the
//     load stream is flattened instead of front-burst, and the register cost
//     (~52 buffer regs) allows 3 CTAs/SM.

#define WID 256
#define HEI 256
#define HW  (WID * HEI)
#define TW  256   // full width: 64 threads x 4 px per row
#define TH  4     // rows per CTA
#define SW  (TW + 4)   // 260 floats per smem row (float4-aligned)
#define SH  (TH + 4)   // 8

__global__ __launch_bounds__(256)
void dynconv5x5_kernel(const float* __restrict__ x,
                       const float* __restrict__ kern,
                       float* __restrict__ out)
{
    __shared__ float tile[SH * SW];

    const int plane = blockIdx.z;           // n*C + c, 0..31
    const int by = blockIdx.y * TH;
    const int tid = threadIdx.x;            // 0..255

    const int lx = tid & 63;                // 64 threads across the row
    const int ly = tid >> 6;                // 4 rows
    const int w0 = lx * 4;                  // first of 4 pixels handled
    const int h  = by + ly;

    // Weight pointer: per tap t, this thread's 4 pixels' weights are one float4.
    const float4* __restrict__ k4 = (const float4*)kern
        + (size_t)plane * 25 * (HW / 4)
        + (size_t)(h * WID + w0) / 4;

    // ---- First half of the weight preload: taps 0..12 (13 LDG.128 in flight) ----
    float4 kv[13];
    #pragma unroll
    for (int t = 0; t < 13; t++) {
        kv[t] = __ldcs(&k4[(size_t)t * (HW / 4)]);
    }

    // Cooperative load of x tile with halo; replicate padding via clamp.
    // (Overlaps with the in-flight weight loads; halo re-reads are L2 hits.)
    const float* __restrict__ xp = x + (size_t)plane * HW;
    #pragma unroll
    for (int i = tid; i < SH * SW; i += 256) {
        int sy = i / SW;
        int sx = i - sy * SW;
        int gy = by + sy - 2; gy = max(0, min(HEI - 1, gy));
        int gx = sx - 2;      gx = max(0, min(WID - 1, gx));
        tile[i] = xp[gy * WID + gx];
    }
    __syncthreads();

    float ax = 0.f, ay = 0.f, az = 0.f, aw = 0.f;

    // Stage the 8-wide x windows for all 5 dy rows once (smem -> regs).
    float s[5][8];
    #pragma unroll
    for (int dy = 0; dy < 5; dy++) {
        const float4* srow = (const float4*)&tile[(ly + dy) * SW + w0];
        float4 s0 = srow[0];
        float4 s1 = srow[1];
        s[dy][0] = s0.x; s[dy][1] = s0.y; s[dy][2] = s0.z; s[dy][3] = s0.w;
        s[dy][4] = s1.x; s[dy][5] = s1.y; s[dy][6] = s1.z; s[dy][7] = s1.w;
    }

    // ---- Consume taps 0..12 while issuing taps 13..24 ----
    // Barrier keeps ptxas from hoisting the second batch above the first
    // batch's consumption (which would recreate the 25-deep front burst).
    asm volatile("" ::: "memory");

    float4 kv2[12];
    #pragma unroll
    for (int t = 0; t < 12; t++) {
        kv2[t] = __ldcs(&k4[(size_t)(t + 13) * (HW / 4)]);
    }

    #pragma unroll
    for (int t = 0; t < 13; t++) {
        int dy = t / 5, dx = t % 5;
        float4 w = kv[t];
        ax += w.x * s[dy][dx + 0];
        ay += w.y * s[dy][dx + 1];
        az += w.z * s[dy][dx + 2];
        aw += w.w * s[dy][dx + 3];
    }

    #pragma unroll
    for (int t = 13; t < 25; t++) {
        int dy = t / 5, dx = t % 5;
        float4 w = kv2[t - 13];
        ax += w.x * s[dy][dx + 0];
        ay += w.y * s[dy][dx + 1];
        az += w.z * s[dy][dx + 2];
        aw += w.w * s[dy][dx + 3];
    }

    // leaky_relu(0.2)
    ax = ax >= 0.f ? ax : 0.2f * ax;
    ay = ay >= 0.f ? ay : 0.2f * ay;
    az = az >= 0.f ? az : 0.2f * az;
    aw = aw >= 0.f ? aw : 0.2f * aw;

    float4 r = make_float4(ax, ay, az, aw);
    __stcs(&((float4*)out)[(size_t)plane * (HW / 4) + (size_t)(h * WID + w0) / 4], r);
}

extern "C" void kernel_launch(void* const* d_in, const int* in_sizes, int n_in,
                              void* d_out, int out_size)
{
    const float* x    = (const float*)d_in[0];   // (4, 8, 256, 256)
    const float* kern = (const float*)d_in[1];   // (4, 200, 256, 256)
    float* out = (float*)d_out;                  // (4, 8, 256, 256)

    dim3 block(256, 1, 1);
    dim3 grid(1, HEI / TH, 32);                  // (1, 64, 32) = 2048 CTAs
    dynconv5x5_kernel<<<grid, block>>>(x, kern, out);
}